// round 3
// baseline (speedup 1.0000x reference)
#include <cuda_runtime.h>
#include <math.h>

#define BQ 4
#define NP 8192
#define SP 512
#define KNN 16
#define FD 128
#define EPSV 1e-5f
typedef unsigned long long u64;

__device__ float g_feats[BQ*NP*FD];
__device__ float g_x[BQ*NP*FD];
__device__ float g_q[BQ*NP*FD];
__device__ int   g_fps[BQ*SP];
__device__ int   g_idx_dn[BQ*SP*KNN];
__device__ float g_new_xyz[BQ*SP*3];
__device__ float g_new_xyzp[BQ*SP*4];
__device__ float g_h0[BQ*SP*KNN*FD];
__device__ float g_h1[BQ*SP*KNN*FD];
__device__ float g_part[64*2*FD];
__device__ float g_m0[FD]; __device__ float g_v0[FD];
__device__ float g_m1[FD]; __device__ float g_v1[FD];
__device__ float g_newfeat[BQ*SP*FD];
__device__ float g_newx[BQ*SP*FD];
__device__ float g_ktab[BQ*SP*FD];
__device__ float g_vtab[BQ*SP*FD];
__device__ int   g_idx_up[BQ*NP*KNN];
__device__ float g_pe[67108864];
__device__ float g_a1[67108864];
__device__ float g_res[BQ*NP*FD];

__global__ void k_layernorm(const float* __restrict__ x, const float* __restrict__ g,
                            const float* __restrict__ b, float* __restrict__ out){
    int row = blockIdx.x, t = threadIdx.x;
    __shared__ float sh[8];
    float v = x[(size_t)row*FD + t];
    float s = v;
    #pragma unroll
    for (int o=16;o;o>>=1) s += __shfl_xor_sync(0xffffffffu, s, o);
    if ((t&31)==0) sh[t>>5]=s;
    __syncthreads();
    float mean = (sh[0]+sh[1]+sh[2]+sh[3]) * (1.0f/FD);
    float d = v - mean;
    float s2 = d*d;
    #pragma unroll
    for (int o=16;o;o>>=1) s2 += __shfl_xor_sync(0xffffffffu, s2, o);
    if ((t&31)==0) sh[4+(t>>5)]=s2;
    __syncthreads();
    float var = (sh[4]+sh[5]+sh[6]+sh[7]) * (1.0f/FD);
    out[(size_t)row*FD+t] = d * rsqrtf(var + EPSV) * g[t] + b[t];
}

__global__ void k_fps(const float* __restrict__ xyzp){
    int b = blockIdx.x, t = threadIdx.x;
    float px[8], py[8], pz[8], md[8];
    #pragma unroll
    for (int j=0;j<8;j++){
        int i = t + j*1024;
        float4 p = ((const float4*)xyzp)[(size_t)b*NP + i];
        px[j]=p.x; py[j]=p.y; pz[j]=p.z; md[j]=1e10f;
    }
    __shared__ u64 warpbest[32];
    __shared__ int s_last;
    if (t==0){ g_fps[b*SP]=0; s_last=0; }
    __syncthreads();
    int last = 0;
    for (int s=1;s<SP;s++){
        const float* pl = xyzp + ((size_t)b*NP + last)*4;
        float lx=pl[0], ly=pl[1], lz=pl[2];
        u64 best=0;
        #pragma unroll
        for (int j=0;j<8;j++){
            float dx=px[j]-lx, dy=py[j]-ly, dz=pz[j]-lz;
            float d = dx*dx+dy*dy+dz*dz;
            md[j] = fminf(md[j], d);
            u64 key = ((u64)__float_as_uint(md[j])<<32) | (unsigned)(NP-1 - (t + j*1024));
            best = key > best ? key : best;
        }
        #pragma unroll
        for (int o=16;o;o>>=1){
            u64 oth = __shfl_xor_sync(0xffffffffu, best, o);
            best = oth > best ? oth : best;
        }
        if ((t&31)==0) warpbest[t>>5]=best;
        __syncthreads();
        if (t<32){
            u64 bb = warpbest[t];
            #pragma unroll
            for (int o=16;o;o>>=1){
                u64 oth = __shfl_xor_sync(0xffffffffu, bb, o);
                bb = oth > bb ? oth : bb;
            }
            if (t==0){ s_last = NP-1 - (int)(bb & 0xffffffffu); g_fps[b*SP+s]=s_last; }
        }
        __syncthreads();
        last = s_last;
    }
}

__global__ void k_knn_dn(const float* __restrict__ xyzp){
    extern __shared__ float sm[];
    float* xs = sm; float* ys = sm+NP; float* zs = sm+2*NP;
    int b = blockIdx.x >> 4, blk = blockIdx.x & 15;
    int t = threadIdx.x, w = t>>5, lane = t&31;
    for (int i=t;i<NP;i+=256){
        float4 p = ((const float4*)xyzp)[(size_t)b*NP + i];
        xs[i]=p.x; ys[i]=p.y; zs[i]=p.z;
    }
    __syncthreads();
    for (int qi=0; qi<4; qi++){
        int s = blk*32 + w*4 + qi;
        int qidx = g_fps[b*SP+s];
        float qx=xs[qidx], qy=ys[qidx], qz=zs[qidx];
        if (lane==0){
            g_new_xyz[(b*SP+s)*3+0]=qx; g_new_xyz[(b*SP+s)*3+1]=qy; g_new_xyz[(b*SP+s)*3+2]=qz;
        }
        u64 kk[16];
        #pragma unroll
        for (int j=0;j<16;j++) kk[j]=~0ull;
        for (int r=lane; r<NP; r+=32){
            float dx=xs[r]-qx, dy=ys[r]-qy, dz=zs[r]-qz;
            float d = dx*dx+dy*dy+dz*dz;
            u64 key = ((u64)__float_as_uint(d)<<32) | (unsigned)r;
            if (key < kk[15]){
                #pragma unroll
                for (int j=0;j<16;j++){
                    u64 lo = kk[j] < key ? kk[j] : key;
                    u64 hi = kk[j] < key ? key : kk[j];
                    kk[j]=lo; key=hi;
                }
            }
        }
        u64 prev = 0;
        for (int r=0;r<16;r++){
            u64 thr = (r==0) ? 0ull : prev + 1ull;
            u64 loc = ~0ull;
            #pragma unroll
            for (int j=0;j<16;j++){
                u64 v = kk[j];
                if (v >= thr && v < loc) loc = v;
            }
            #pragma unroll
            for (int o=16;o;o>>=1){
                u64 oth = __shfl_xor_sync(0xffffffffu, loc, o);
                loc = oth < loc ? oth : loc;
            }
            prev = loc;
            if (lane==0){
                int id = (int)(loc & 0xffffffffu);
                g_idx_dn[(b*SP+s)*KNN + r] = id;
                if (r==0) ((float4*)g_new_xyzp)[b*SP+s] = ((const float4*)xyzp)[(size_t)b*NP + id];
            }
        }
    }
}

__global__ void k_knn_up(const float* __restrict__ xyzp){
    __shared__ float rx[SP], ry[SP], rz[SP];
    int t=threadIdx.x, w=t>>5, lane=t&31;
    int b = blockIdx.x >> 10;
    int n = (blockIdx.x & 1023)*8 + w;
    for (int i=t;i<SP;i+=256){
        rx[i]=g_new_xyz[(i+b*SP)*3+0]; ry[i]=g_new_xyz[(i+b*SP)*3+1]; rz[i]=g_new_xyz[(i+b*SP)*3+2];
    }
    __syncthreads();
    float4 qp = ((const float4*)xyzp)[(size_t)b*NP + n];
    u64 kk[16];
    #pragma unroll
    for (int j=0;j<16;j++) kk[j]=~0ull;
    for (int r=lane; r<SP; r+=32){
        float dx=rx[r]-qp.x, dy=ry[r]-qp.y, dz=rz[r]-qp.z;
        float d = dx*dx+dy*dy+dz*dz;
        u64 key = ((u64)__float_as_uint(d)<<32) | (unsigned)r;
        if (key < kk[15]){
            #pragma unroll
            for (int j=0;j<16;j++){
                u64 lo = kk[j] < key ? kk[j] : key;
                u64 hi = kk[j] < key ? key : kk[j];
                kk[j]=lo; key=hi;
            }
        }
    }
    u64 prev = 0;
    for (int r=0;r<16;r++){
        u64 thr = (r==0) ? 0ull : prev + 1ull;
        u64 loc = ~0ull;
        #pragma unroll
        for (int j=0;j<16;j++){
            u64 v = kk[j];
            if (v >= thr && v < loc) loc = v;
        }
        #pragma unroll
        for (int o=16;o;o>>=1){
            u64 oth = __shfl_xor_sync(0xffffffffu, loc, o);
            loc = oth < loc ? oth : loc;
        }
        prev = loc;
        if (lane==0) g_idx_up[((size_t)b*NP+n)*KNN + r] = (int)(loc & 0xffffffffu);
    }
}

__device__ __forceinline__ void mm_tile(const float* Wsh, const float* Ash,
                                        int kg, int cg, float acc[4][4], int kdim){
    #pragma unroll 4
    for (int i=0;i<kdim;i++){
        float4 wv = *(const float4*)(Wsh + i*128 + (cg<<2));
        float a0=Ash[i*16+(kg<<2)+0];
        float a1=Ash[i*16+(kg<<2)+1];
        float a2=Ash[i*16+(kg<<2)+2];
        float a3=Ash[i*16+(kg<<2)+3];
        acc[0][0]+=a0*wv.x; acc[0][1]+=a0*wv.y; acc[0][2]+=a0*wv.z; acc[0][3]+=a0*wv.w;
        acc[1][0]+=a1*wv.x; acc[1][1]+=a1*wv.y; acc[1][2]+=a1*wv.z; acc[1][3]+=a1*wv.w;
        acc[2][0]+=a2*wv.x; acc[2][1]+=a2*wv.y; acc[2][2]+=a2*wv.z; acc[2][3]+=a2*wv.w;
        acc[3][0]+=a3*wv.x; acc[3][1]+=a3*wv.y; acc[3][2]+=a3*wv.z; acc[3][3]+=a3*wv.w;
    }
}

__global__ void k_h0(const float* __restrict__ xyzp, const float* __restrict__ tw0,
                     const float* __restrict__ tb0){
    extern __shared__ float sm[];
    float* Wsh = sm;
    float* Ash = Wsh + 131*128;
    __shared__ int idxs[16];
    __shared__ float nxyz[3];
    int t = threadIdx.x, bs = blockIdx.x, b = bs >> 9;
    for (int i=t;i<131*128;i+=128) Wsh[i]=tw0[i];
    if (t<16) idxs[t] = g_idx_dn[bs*KNN+t];
    if (t<3)  nxyz[t] = g_new_xyz[bs*3+t];
    __syncthreads();
    #pragma unroll
    for (int k=0;k<KNN;k++){
        int id = idxs[k];
        float v;
        if (t<3) v = xyzp[((size_t)b*NP+id)*4 + t] - nxyz[t];
        else     v = g_feats[((size_t)b*NP+id)*FD + (t-3)];
        Ash[t*16+k]=v;
        if (t<3) Ash[(128+t)*16+k] = g_feats[((size_t)b*NP+id)*FD + (125+t)];
    }
    __syncthreads();
    int kg=t>>5, cg=t&31;
    float acc[4][4]={};
    mm_tile(Wsh, Ash, kg, cg, acc, 131);
    float4 bv = *(const float4*)(tb0 + (cg<<2));
    #pragma unroll
    for (int kk=0;kk<4;kk++){
        float4 o = make_float4(acc[kk][0]+bv.x, acc[kk][1]+bv.y, acc[kk][2]+bv.z, acc[kk][3]+bv.w);
        ((float4*)g_h0)[((size_t)bs*KNN + 4*kg+kk)*32 + cg] = o;
    }
}

__global__ void k_stats_part(const float* __restrict__ X, int nrows, float* __restrict__ part){
    int t=threadIdx.x, blk=blockIdx.x;
    int chunk = nrows/64;
    float s=0.f, s2=0.f;
    for (int r=0;r<chunk;r++){
        float v = X[((size_t)(blk*chunk+r))*FD + t];
        s += v; s2 += v*v;
    }
    part[blk*2*FD + t] = s;
    part[blk*2*FD + FD + t] = s2;
}
__global__ void k_stats_final(const float* __restrict__ part, int nrows,
                              float* __restrict__ mean, float* __restrict__ var){
    int t=threadIdx.x;
    float s=0.f, s2=0.f;
    for (int i=0;i<64;i++){ s += part[i*2*FD+t]; s2 += part[i*2*FD+FD+t]; }
    float m = s/(float)nrows;
    mean[t]=m;
    var[t]=s2/(float)nrows - m*m;
}

__global__ void k_gemm128(const float* __restrict__ A, const float* __restrict__ W,
                          const float* __restrict__ bias, float* __restrict__ C,
                          int flags,
                          const float* __restrict__ bnm, const float* __restrict__ bnv,
                          const float* __restrict__ bng, const float* __restrict__ bnb,
                          const float* __restrict__ addsrc){
    extern __shared__ float sm[];
    float* Wsh = sm; float* Ash = sm + 128*128;
    int t=threadIdx.x;
    size_t row0 = (size_t)blockIdx.x*16;
    for (int i=t;i<4096;i+=128) ((float4*)Wsh)[i]=((const float4*)W)[i];
    float bm=0.f, brv=1.f, bg=1.f, bb=0.f;
    if (flags&2){ bm=bnm[t]; brv=rsqrtf(bnv[t]+EPSV); bg=bng[t]; bb=bnb[t]; }
    #pragma unroll
    for (int k=0;k<16;k++){
        float v = A[(row0+k)*FD + t];
        if (flags&2) v = fmaxf((v-bm)*brv*bg + bb, 0.f);
        Ash[t*16+k]=v;
    }
    __syncthreads();
    int kg=t>>5, cg=t&31;
    float acc[4][4]={};
    mm_tile(Wsh, Ash, kg, cg, acc, 128);
    float4 bv = bias ? *(const float4*)(bias + (cg<<2)) : make_float4(0.f,0.f,0.f,0.f);
    #pragma unroll
    for (int kk=0;kk<4;kk++){
        size_t r = row0 + 4*kg + kk;
        float4 o = make_float4(acc[kk][0]+bv.x, acc[kk][1]+bv.y, acc[kk][2]+bv.z, acc[kk][3]+bv.w);
        if (flags&1){ o.x=fmaxf(o.x,0.f); o.y=fmaxf(o.y,0.f); o.z=fmaxf(o.z,0.f); o.w=fmaxf(o.w,0.f); }
        if (flags&4){
            float4 ad = ((const float4*)addsrc)[r*32 + cg];
            o.x+=ad.x; o.y+=ad.y; o.z+=ad.z; o.w+=ad.w;
        }
        ((float4*)C)[r*32 + cg] = o;
    }
}

__global__ void k_maxpool(const float* __restrict__ bg, const float* __restrict__ bb){
    int bs = blockIdx.x, t = threadIdx.x;
    float m = g_m1[t], rv = rsqrtf(g_v1[t]+EPSV), ga=bg[t], be=bb[t];
    float best = -1e30f;
    #pragma unroll
    for (int k=0;k<KNN;k++){
        float v = g_h1[((size_t)bs*KNN+k)*FD + t];
        v = fmaxf((v-m)*rv*ga + be, 0.f);
        best = fmaxf(best, v);
    }
    g_newfeat[(size_t)bs*FD+t] = best;
}

__global__ void k_posenc(const float* __restrict__ xyzp, const float* __restrict__ pe_w1,
                         const float* __restrict__ pe_b1, const float* __restrict__ pe_w2,
                         const float* __restrict__ pe_b2){
    extern __shared__ float sm[];
    float* Wsh   = sm;
    float* Ash   = Wsh + 16384;
    float* pw1   = Ash + 2048;
    float* pdiff = pw1 + 512;
    int t=threadIdx.x, bn=blockIdx.x, b=bn>>13;
    for (int i=t;i<4096;i+=128) ((float4*)Wsh)[i]=((const float4*)pe_w2)[i];
    pw1[t]=pe_w1[t]; pw1[128+t]=pe_w1[128+t]; pw1[256+t]=pe_w1[256+t]; pw1[384+t]=pe_w1[384+t];
    if (t<16){
        int id = g_idx_up[(size_t)bn*KNN+t];
        float4 qp = ((const float4*)xyzp)[bn];
        float4 np = ((const float4*)g_new_xyzp)[b*SP + id];
        pdiff[t*4+0]=qp.x-np.x; pdiff[t*4+1]=qp.y-np.y;
        pdiff[t*4+2]=qp.z-np.z; pdiff[t*4+3]=qp.w-np.w;
    }
    __syncthreads();
    {
        float w0=pw1[t], w1=pw1[128+t], w2=pw1[256+t], w3=pw1[384+t], b1=pe_b1[t];
        #pragma unroll
        for (int k=0;k<KNN;k++){
            float v = b1 + pdiff[k*4+0]*w0 + pdiff[k*4+1]*w1 + pdiff[k*4+2]*w2 + pdiff[k*4+3]*w3;
            Ash[t*16+k] = fmaxf(v, 0.f);
        }
    }
    __syncthreads();
    int kg=t>>5, cg=t&31;
    float acc[4][4]={};
    mm_tile(Wsh, Ash, kg, cg, acc, 128);
    float4 bv = *(const float4*)(pe_b2 + (cg<<2));
    #pragma unroll
    for (int kk=0;kk<4;kk++){
        float4 o = make_float4(acc[kk][0]+bv.x, acc[kk][1]+bv.y, acc[kk][2]+bv.z, acc[kk][3]+bv.w);
        ((float4*)g_pe)[((size_t)bn*KNN + 4*kg+kk)*32 + cg] = o;
    }
}

__global__ void k_att1(const float* __restrict__ at_w1, const float* __restrict__ at_b1){
    extern __shared__ float sm[];
    float* Wsh = sm; float* Ash = sm + 16384;
    __shared__ int idxs[16];
    int t=threadIdx.x, bn=blockIdx.x, b=bn>>13;
    for (int i=t;i<4096;i+=128) ((float4*)Wsh)[i]=((const float4*)at_w1)[i];
    if (t<16) idxs[t] = g_idx_up[(size_t)bn*KNN+t];
    __syncthreads();
    float qv = g_q[(size_t)bn*FD + t];
    #pragma unroll
    for (int k=0;k<KNN;k++){
        int id = idxs[k];
        Ash[t*16+k] = qv - g_ktab[((size_t)(b*SP+id))*FD + t] + g_pe[(((size_t)bn)*KNN+k)*FD + t];
    }
    __syncthreads();
    int kg=t>>5, cg=t&31;
    float acc[4][4]={};
    mm_tile(Wsh, Ash, kg, cg, acc, 128);
    float4 bv = *(const float4*)(at_b1 + (cg<<2));
    #pragma unroll
    for (int kk=0;kk<4;kk++){
        float4 o = make_float4(fmaxf(acc[kk][0]+bv.x,0.f), fmaxf(acc[kk][1]+bv.y,0.f),
                               fmaxf(acc[kk][2]+bv.z,0.f), fmaxf(acc[kk][3]+bv.w,0.f));
        ((float4*)g_a1)[((size_t)bn*KNN + 4*kg+kk)*32 + cg] = o;
    }
}

__global__ void k_att2(const float* __restrict__ at_w2, const float* __restrict__ at_b2){
    extern __shared__ float sm[];
    float* Wsh = sm; float* Ash = sm + 16384; float* a2sh = Ash + 2048;
    __shared__ int idxs[16];
    int t=threadIdx.x, bn=blockIdx.x, b=bn>>13;
    for (int i=t;i<4096;i+=128) ((float4*)Wsh)[i]=((const float4*)at_w2)[i];
    if (t<16) idxs[t] = g_idx_up[(size_t)bn*KNN+t];
    #pragma unroll
    for (int k=0;k<KNN;k++)
        Ash[t*16+k] = g_a1[(((size_t)bn)*KNN+k)*FD + t];
    __syncthreads();
    int kg=t>>5, cg=t&31;
    float acc[4][4]={};
    mm_tile(Wsh, Ash, kg, cg, acc, 128);
    float4 bv = *(const float4*)(at_b2 + (cg<<2));
    #pragma unroll
    for (int kk=0;kk<4;kk++){
        float4 o = make_float4(acc[kk][0]+bv.x, acc[kk][1]+bv.y, acc[kk][2]+bv.z, acc[kk][3]+bv.w);
        ((float4*)(a2sh + (4*kg+kk)*128))[cg] = o;
    }
    __syncthreads();
    const float inv = 0.08838834764831845f;
    float s[16], mx=-1e30f;
    #pragma unroll
    for (int k=0;k<KNN;k++){ s[k] = a2sh[k*128+t]*inv; mx = fmaxf(mx, s[k]); }
    float den=0.f;
    #pragma unroll
    for (int k=0;k<KNN;k++){ s[k] = expf(s[k]-mx); den += s[k]; }
    float rden = 1.f/den;
    float r=0.f;
    #pragma unroll
    for (int k=0;k<KNN;k++){
        int id = idxs[k];
        float v = g_vtab[((size_t)(b*SP+id))*FD + t] + g_pe[(((size_t)bn)*KNN+k)*FD + t];
        r += (s[k]*rden) * v;
    }
    g_res[(size_t)bn*FD + t] = r;
}

extern "C" void kernel_launch(void* const* d_in, const int* in_sizes, int n_in,
                              void* d_out, int out_size){
    const float* xyzp     = (const float*)d_in[0];
    const float* features = (const float*)d_in[1];
    const float* ln_g     = (const float*)d_in[2];
    const float* ln_b     = (const float*)d_in[3];
    const float* td_w0    = (const float*)d_in[4];
    const float* td_b0    = (const float*)d_in[5];
    const float* td_bn0_g = (const float*)d_in[6];
    const float* td_bn0_b = (const float*)d_in[7];
    const float* td_w1    = (const float*)d_in[8];
    const float* td_b1    = (const float*)d_in[9];
    const float* td_bn1_g = (const float*)d_in[10];
    const float* td_bn1_b = (const float*)d_in[11];
    const float* w_kern   = (const float*)d_in[12];
    const float* b_kern   = (const float*)d_in[13];
    const float* w_gkern  = (const float*)d_in[14];
    const float* b_gkern  = (const float*)d_in[15];
    const float* w_agg    = (const float*)d_in[16];
    const float* b_agg    = (const float*)d_in[17];
    const float* w_q      = (const float*)d_in[18];
    const float* w_k      = (const float*)d_in[19];
    const float* w_v      = (const float*)d_in[20];
    const float* pe_w1    = (const float*)d_in[21];
    const float* pe_b1    = (const float*)d_in[22];
    const float* pe_w2    = (const float*)d_in[23];
    const float* pe_b2    = (const float*)d_in[24];
    const float* at_w1    = (const float*)d_in[25];
    const float* at_b1    = (const float*)d_in[26];
    const float* at_w2    = (const float*)d_in[27];
    const float* at_b2    = (const float*)d_in[28];
    float* out = (float*)d_out;

    float *p_feats,*p_x,*p_q,*p_h0,*p_h1,*p_part,*p_m0,*p_v0,*p_m1,*p_v1;
    float *p_newfeat,*p_newx,*p_ktab,*p_vtab,*p_res;
    cudaGetSymbolAddress((void**)&p_feats,   g_feats);
    cudaGetSymbolAddress((void**)&p_x,       g_x);
    cudaGetSymbolAddress((void**)&p_q,       g_q);
    cudaGetSymbolAddress((void**)&p_h0,      g_h0);
    cudaGetSymbolAddress((void**)&p_h1,      g_h1);
    cudaGetSymbolAddress((void**)&p_part,    g_part);
    cudaGetSymbolAddress((void**)&p_m0,      g_m0);
    cudaGetSymbolAddress((void**)&p_v0,      g_v0);
    cudaGetSymbolAddress((void**)&p_m1,      g_m1);
    cudaGetSymbolAddress((void**)&p_v1,      g_v1);
    cudaGetSymbolAddress((void**)&p_newfeat, g_newfeat);
    cudaGetSymbolAddress((void**)&p_newx,    g_newx);
    cudaGetSymbolAddress((void**)&p_ktab,    g_ktab);
    cudaGetSymbolAddress((void**)&p_vtab,    g_vtab);
    cudaGetSymbolAddress((void**)&p_res,     g_res);

    const int SM_KNN_DN = 3*NP*4;
    const int SM_H0     = (131*128 + 131*16)*4;
    const int SM_GEMM   = (128*128 + 128*16)*4;
    const int SM_PE     = (128*128 + 128*16 + 512 + 64)*4;
    const int SM_ATT2   = (128*128 + 128*16 + 16*128)*4;
    static int attr_done = 0;
    if (!attr_done){
        cudaFuncSetAttribute(k_knn_dn,  cudaFuncAttributeMaxDynamicSharedMemorySize, SM_KNN_DN);
        cudaFuncSetAttribute(k_h0,      cudaFuncAttributeMaxDynamicSharedMemorySize, SM_H0);
        cudaFuncSetAttribute(k_gemm128, cudaFuncAttributeMaxDynamicSharedMemorySize, SM_GEMM);
        cudaFuncSetAttribute(k_posenc,  cudaFuncAttributeMaxDynamicSharedMemorySize, SM_PE);
        cudaFuncSetAttribute(k_att1,    cudaFuncAttributeMaxDynamicSharedMemorySize, SM_GEMM);
        cudaFuncSetAttribute(k_att2,    cudaFuncAttributeMaxDynamicSharedMemorySize, SM_ATT2);
        attr_done = 1;
    }

    k_layernorm<<<BQ*NP, 128>>>(features, ln_g, ln_b, p_feats);
    k_fps<<<BQ, 1024>>>(xyzp);
    k_knn_dn<<<BQ*16, 256, SM_KNN_DN>>>(xyzp);
    k_knn_up<<<BQ*1024, 256>>>(xyzp);
    k_h0<<<BQ*SP, 128, SM_H0>>>(xyzp, td_w0, td_b0);
    k_stats_part<<<64, 128>>>(p_h0, BQ*SP*KNN, p_part);
    k_stats_final<<<1, 128>>>(p_part, BQ*SP*KNN, p_m0, p_v0);
    k_gemm128<<<BQ*SP*KNN/16, 128, SM_GEMM>>>(p_h0, td_w1, td_b1, p_h1, 2,
                                              p_m0, p_v0, td_bn0_g, td_bn0_b, 0);
    k_stats_part<<<64, 128>>>(p_h1, BQ*SP*KNN, p_part);
    k_stats_final<<<1, 128>>>(p_part, BQ*SP*KNN, p_m1, p_v1);
    k_maxpool<<<BQ*SP, 128>>>(td_bn1_g, td_bn1_b);
    k_gemm128<<<BQ*NP/16, 128, SM_GEMM>>>(p_feats, w_kern, b_kern, p_x, 0, 0,0,0,0, 0);
    k_gemm128<<<BQ*NP/16, 128, SM_GEMM>>>(p_x, w_q, 0, p_q, 0, 0,0,0,0, 0);
    k_gemm128<<<BQ*SP/16, 128, SM_GEMM>>>(p_newfeat, w_gkern, b_gkern, p_newx, 0, 0,0,0,0, 0);
    k_gemm128<<<BQ*SP/16, 128, SM_GEMM>>>(p_newx, w_k, 0, p_ktab, 0, 0,0,0,0, 0);
    k_gemm128<<<BQ*SP/16, 128, SM_GEMM>>>(p_newx, w_v, 0, p_vtab, 0, 0,0,0,0, 0);
    k_posenc<<<BQ*NP, 128, SM_PE>>>(xyzp, pe_w1, pe_b1, pe_w2, pe_b2);
    k_att1<<<BQ*NP, 128, SM_GEMM>>>(at_w1, at_b1);
    k_att2<<<BQ*NP, 128, SM_ATT2>>>(at_w2, at_b2);
    k_gemm128<<<BQ*NP/16, 128, SM_GEMM>>>(p_res, w_agg, b_agg, out, 4, 0,0,0,0, p_feats);
}

// round 4
// speedup vs baseline: 1.1241x; 1.1241x over previous
#include <cuda_runtime.h>
#include <math.h>

#define BQ 4
#define NP 8192
#define SP 512
#define KNN 16
#define FD 128
#define EPSV 1e-5f
typedef unsigned long long u64;

__device__ float g_feats[BQ*NP*FD];
__device__ float g_q[BQ*NP*FD];
__device__ int   g_fps[BQ*SP];
__device__ int   g_idx_dn[BQ*SP*KNN];
__device__ float g_new_xyz[BQ*SP*3];
__device__ float g_new_xyzp[BQ*SP*4];
__device__ float g_h0[BQ*SP*KNN*FD];
__device__ float g_h1[BQ*SP*KNN*FD];
__device__ float g_part[64*2*FD];
__device__ float g_m0[FD]; __device__ float g_v0[FD];
__device__ float g_m1[FD]; __device__ float g_v1[FD];
__device__ float g_newfeat[BQ*SP*FD];
__device__ float g_newx[BQ*SP*FD];
__device__ float g_ktab[BQ*SP*FD];
__device__ float g_vtab[BQ*SP*FD];
__device__ int   g_idx_up[BQ*NP*KNN];
__device__ float g_res[BQ*NP*FD];
__device__ float g_wqc[FD*FD];
__device__ float g_bqc[FD];

// ---------- f32x2 packed helpers ----------
__device__ __forceinline__ u64 pk2(float a){
    u64 r; asm("mov.b64 %0,{%1,%1};" : "=l"(r) : "f"(a)); return r;
}
__device__ __forceinline__ void fma2(u64& d, u64 a, u64 b){
    asm("fma.rn.f32x2 %0,%1,%2,%0;" : "+l"(d) : "l"(a), "l"(b));
}
__device__ __forceinline__ void upk(u64 v, float& lo, float& hi){
    asm("mov.b64 {%0,%1},%2;" : "=f"(lo), "=f"(hi) : "l"(v));
}

// 32-row x 128-col GEMM core. Ash layout [32 rows][128 K], Wsh [128 K][128 cols].
// Thread (kg=t>>5, cg=t&31) computes rows 8*kg..8*kg+7, cols 4*cg..4*cg+3.
__device__ __forceinline__ void gemm32_core(const float* __restrict__ Wsh,
                                            const float* __restrict__ Ash,
                                            int kg, int cg, u64 acc[8][2]){
    #pragma unroll
    for (int r=0;r<8;r++){ acc[r][0]=0ull; acc[r][1]=0ull; }
    const float* arow = Ash + (kg<<3)*FD;
    #pragma unroll 4
    for (int i=0;i<FD;i++){
        ulonglong2 w = *(const ulonglong2*)(Wsh + i*FD + (cg<<2));
        #pragma unroll
        for (int r=0;r<8;r++){
            u64 a2 = pk2(arow[r*FD + i]);
            fma2(acc[r][0], a2, w.x);
            fma2(acc[r][1], a2, w.y);
        }
    }
}

// ---------------- layernorm ----------------
__global__ void k_layernorm(const float* __restrict__ x, const float* __restrict__ g,
                            const float* __restrict__ b, float* __restrict__ out){
    int row = blockIdx.x, t = threadIdx.x;
    __shared__ float sh[8];
    float v = x[(size_t)row*FD + t];
    float s = v;
    #pragma unroll
    for (int o=16;o;o>>=1) s += __shfl_xor_sync(0xffffffffu, s, o);
    if ((t&31)==0) sh[t>>5]=s;
    __syncthreads();
    float mean = (sh[0]+sh[1]+sh[2]+sh[3]) * (1.0f/FD);
    float d = v - mean;
    float s2 = d*d;
    #pragma unroll
    for (int o=16;o;o>>=1) s2 += __shfl_xor_sync(0xffffffffu, s2, o);
    if ((t&31)==0) sh[4+(t>>5)]=s2;
    __syncthreads();
    float var = (sh[4]+sh[5]+sh[6]+sh[7]) * (1.0f/FD);
    out[(size_t)row*FD+t] = d * rsqrtf(var + EPSV) * g[t] + b[t];
}

// ---------------- FPS (last point read from smem) ----------------
__global__ void k_fps(const float* __restrict__ xyzp){
    extern __shared__ float sm[];
    float* xs = sm; float* ys = sm + NP; float* zs = sm + 2*NP;
    int b = blockIdx.x, t = threadIdx.x;
    float px[8], py[8], pz[8], md[8];
    #pragma unroll
    for (int j=0;j<8;j++){
        int i = t + j*1024;
        float4 p = ((const float4*)xyzp)[(size_t)b*NP + i];
        px[j]=p.x; py[j]=p.y; pz[j]=p.z; md[j]=1e10f;
        xs[i]=p.x; ys[i]=p.y; zs[i]=p.z;
    }
    __shared__ u64 warpbest[32];
    __shared__ int s_last;
    if (t==0){ g_fps[b*SP]=0; s_last=0; }
    __syncthreads();
    int last = 0;
    for (int s=1;s<SP;s++){
        float lx=xs[last], ly=ys[last], lz=zs[last];
        u64 best=0;
        #pragma unroll
        for (int j=0;j<8;j++){
            float dx=px[j]-lx, dy=py[j]-ly, dz=pz[j]-lz;
            float d = dx*dx+dy*dy+dz*dz;
            md[j] = fminf(md[j], d);
            u64 key = ((u64)__float_as_uint(md[j])<<32) | (unsigned)(NP-1 - (t + j*1024));
            best = key > best ? key : best;
        }
        #pragma unroll
        for (int o=16;o;o>>=1){
            u64 oth = __shfl_xor_sync(0xffffffffu, best, o);
            best = oth > best ? oth : best;
        }
        if ((t&31)==0) warpbest[t>>5]=best;
        __syncthreads();
        if (t<32){
            u64 bb = warpbest[t];
            #pragma unroll
            for (int o=16;o;o>>=1){
                u64 oth = __shfl_xor_sync(0xffffffffu, bb, o);
                bb = oth > bb ? oth : bb;
            }
            if (t==0){ s_last = NP-1 - (int)(bb & 0xffffffffu); g_fps[b*SP+s]=s_last; }
        }
        __syncthreads();
        last = s_last;
    }
}

// ---------------- knn: 512 fps pts vs 8192 refs ----------------
__global__ void k_knn_dn(const float* __restrict__ xyzp){
    extern __shared__ float sm[];
    float* xs = sm; float* ys = sm+NP; float* zs = sm+2*NP;
    int b = blockIdx.x >> 4, blk = blockIdx.x & 15;
    int t = threadIdx.x, w = t>>5, lane = t&31;
    for (int i=t;i<NP;i+=256){
        float4 p = ((const float4*)xyzp)[(size_t)b*NP + i];
        xs[i]=p.x; ys[i]=p.y; zs[i]=p.z;
    }
    __syncthreads();
    for (int qi=0; qi<4; qi++){
        int s = blk*32 + w*4 + qi;
        int qidx = g_fps[b*SP+s];
        float qx=xs[qidx], qy=ys[qidx], qz=zs[qidx];
        if (lane==0){
            g_new_xyz[(b*SP+s)*3+0]=qx; g_new_xyz[(b*SP+s)*3+1]=qy; g_new_xyz[(b*SP+s)*3+2]=qz;
        }
        u64 kk[16];
        #pragma unroll
        for (int j=0;j<16;j++) kk[j]=~0ull;
        for (int r=lane; r<NP; r+=32){
            float dx=xs[r]-qx, dy=ys[r]-qy, dz=zs[r]-qz;
            float d = dx*dx+dy*dy+dz*dz;
            u64 key = ((u64)__float_as_uint(d)<<32) | (unsigned)r;
            if (key < kk[15]){
                #pragma unroll
                for (int j=0;j<16;j++){
                    u64 lo = kk[j] < key ? kk[j] : key;
                    u64 hi = kk[j] < key ? key : kk[j];
                    kk[j]=lo; key=hi;
                }
            }
        }
        u64 prev = 0;
        for (int r=0;r<16;r++){
            u64 thr = (r==0) ? 0ull : prev + 1ull;
            u64 loc = ~0ull;
            #pragma unroll
            for (int j=0;j<16;j++){
                u64 v = kk[j];
                if (v >= thr && v < loc) loc = v;
            }
            #pragma unroll
            for (int o=16;o;o>>=1){
                u64 oth = __shfl_xor_sync(0xffffffffu, loc, o);
                loc = oth < loc ? oth : loc;
            }
            prev = loc;
            if (lane==0){
                int id = (int)(loc & 0xffffffffu);
                g_idx_dn[(b*SP+s)*KNN + r] = id;
                if (r==0) ((float4*)g_new_xyzp)[b*SP+s] = ((const float4*)xyzp)[(size_t)b*NP + id];
            }
        }
    }
}

// ---------------- knn: 8192 pts vs 512 fps pts ----------------
__global__ void k_knn_up(const float* __restrict__ xyzp){
    __shared__ float rx[SP], ry[SP], rz[SP];
    int t=threadIdx.x, w=t>>5, lane=t&31;
    int b = blockIdx.x >> 10;
    int n = (blockIdx.x & 1023)*8 + w;
    for (int i=t;i<SP;i+=256){
        rx[i]=g_new_xyz[(i+b*SP)*3+0]; ry[i]=g_new_xyz[(i+b*SP)*3+1]; rz[i]=g_new_xyz[(i+b*SP)*3+2];
    }
    __syncthreads();
    float4 qp = ((const float4*)xyzp)[(size_t)b*NP + n];
    u64 kk[16];
    #pragma unroll
    for (int j=0;j<16;j++) kk[j]=~0ull;
    for (int r=lane; r<SP; r+=32){
        float dx=rx[r]-qp.x, dy=ry[r]-qp.y, dz=rz[r]-qp.z;
        float d = dx*dx+dy*dy+dz*dz;
        u64 key = ((u64)__float_as_uint(d)<<32) | (unsigned)r;
        if (key < kk[15]){
            #pragma unroll
            for (int j=0;j<16;j++){
                u64 lo = kk[j] < key ? kk[j] : key;
                u64 hi = kk[j] < key ? key : kk[j];
                kk[j]=lo; key=hi;
            }
        }
    }
    u64 prev = 0;
    for (int r=0;r<16;r++){
        u64 thr = (r==0) ? 0ull : prev + 1ull;
        u64 loc = ~0ull;
        #pragma unroll
        for (int j=0;j<16;j++){
            u64 v = kk[j];
            if (v >= thr && v < loc) loc = v;
        }
        #pragma unroll
        for (int o=16;o;o>>=1){
            u64 oth = __shfl_xor_sync(0xffffffffu, loc, o);
            loc = oth < loc ? oth : loc;
        }
        prev = loc;
        if (lane==0) g_idx_up[((size_t)b*NP+n)*KNN + r] = (int)(loc & 0xffffffffu);
    }
}

// ---------------- scalar tile core for 131-K h0 ----------------
__device__ __forceinline__ void mm_tile(const float* Wsh, const float* Ash,
                                        int kg, int cg, float acc[4][4], int kdim){
    #pragma unroll 4
    for (int i=0;i<kdim;i++){
        float4 wv = *(const float4*)(Wsh + i*128 + (cg<<2));
        float a0=Ash[i*16+(kg<<2)+0];
        float a1=Ash[i*16+(kg<<2)+1];
        float a2=Ash[i*16+(kg<<2)+2];
        float a3=Ash[i*16+(kg<<2)+3];
        acc[0][0]+=a0*wv.x; acc[0][1]+=a0*wv.y; acc[0][2]+=a0*wv.z; acc[0][3]+=a0*wv.w;
        acc[1][0]+=a1*wv.x; acc[1][1]+=a1*wv.y; acc[1][2]+=a1*wv.z; acc[1][3]+=a1*wv.w;
        acc[2][0]+=a2*wv.x; acc[2][1]+=a2*wv.y; acc[2][2]+=a2*wv.z; acc[2][3]+=a2*wv.w;
        acc[3][0]+=a3*wv.x; acc[3][1]+=a3*wv.y; acc[3][2]+=a3*wv.z; acc[3][3]+=a3*wv.w;
    }
}

__global__ void k_h0(const float* __restrict__ xyzp, const float* __restrict__ tw0,
                     const float* __restrict__ tb0){
    extern __shared__ float sm[];
    float* Wsh = sm;
    float* Ash = Wsh + 131*128;
    __shared__ int idxs[16];
    __shared__ float nxyz[3];
    int t = threadIdx.x, bs = blockIdx.x, b = bs >> 9;
    for (int i=t;i<131*128;i+=128) Wsh[i]=tw0[i];
    if (t<16) idxs[t] = g_idx_dn[bs*KNN+t];
    if (t<3)  nxyz[t] = g_new_xyz[bs*3+t];
    __syncthreads();
    #pragma unroll
    for (int k=0;k<KNN;k++){
        int id = idxs[k];
        float v;
        if (t<3) v = xyzp[((size_t)b*NP+id)*4 + t] - nxyz[t];
        else     v = g_feats[((size_t)b*NP+id)*FD + (t-3)];
        Ash[t*16+k]=v;
        if (t<3) Ash[(128+t)*16+k] = g_feats[((size_t)b*NP+id)*FD + (125+t)];
    }
    __syncthreads();
    int kg=t>>5, cg=t&31;
    float acc[4][4]={};
    mm_tile(Wsh, Ash, kg, cg, acc, 131);
    float4 bv = *(const float4*)(tb0 + (cg<<2));
    #pragma unroll
    for (int kk=0;kk<4;kk++){
        float4 o = make_float4(acc[kk][0]+bv.x, acc[kk][1]+bv.y, acc[kk][2]+bv.z, acc[kk][3]+bv.w);
        ((float4*)g_h0)[((size_t)bs*KNN + 4*kg+kk)*32 + cg] = o;
    }
}

// ---------------- batchnorm stats ----------------
__global__ void k_stats_part(const float* __restrict__ X, int nrows, float* __restrict__ part){
    int t=threadIdx.x, blk=blockIdx.x;
    int chunk = nrows/64;
    float s=0.f, s2=0.f;
    for (int r=0;r<chunk;r++){
        float v = X[((size_t)(blk*chunk+r))*FD + t];
        s += v; s2 += v*v;
    }
    part[blk*2*FD + t] = s;
    part[blk*2*FD + FD + t] = s2;
}
__global__ void k_stats_final(const float* __restrict__ part, int nrows,
                              float* __restrict__ mean, float* __restrict__ var){
    int t=threadIdx.x;
    float s=0.f, s2=0.f;
    for (int i=0;i<64;i++){ s += part[i*2*FD+t]; s2 += part[i*2*FD+FD+t]; }
    float m = s/(float)nrows;
    mean[t]=m;
    var[t]=s2/(float)nrows - m*m;
}

// ---------------- 32-row f32x2 GEMM (128->128) ----------------
// flags: 1 relu out, 2 bn+relu on input, 4 add addsrc
__global__ __launch_bounds__(128) void k_gemm128(
        const float* __restrict__ A, const float* __restrict__ W,
        const float* __restrict__ bias, float* __restrict__ C, int flags,
        const float* __restrict__ bnm, const float* __restrict__ bnv,
        const float* __restrict__ bng, const float* __restrict__ bnb,
        const float* __restrict__ addsrc){
    extern __shared__ float sm[];
    float* Wsh = sm; float* Ash = sm + 16384;
    int t=threadIdx.x;
    size_t row0 = (size_t)blockIdx.x*32;
    for (int i=t;i<4096;i+=128) ((float4*)Wsh)[i]=((const float4*)W)[i];
    float bm=0.f, brv=1.f, bg=1.f, bb=0.f;
    if (flags&2){ bm=bnm[t]; brv=rsqrtf(bnv[t]+EPSV); bg=bng[t]; bb=bnb[t]; }
    #pragma unroll
    for (int k=0;k<32;k++){
        float v = A[(row0+k)*FD + t];
        if (flags&2) v = fmaxf((v-bm)*brv*bg + bb, 0.f);
        Ash[k*FD+t]=v;
    }
    __syncthreads();
    int kg=t>>5, cg=t&31;
    u64 acc[8][2];
    gemm32_core(Wsh, Ash, kg, cg, acc);
    float4 bv = bias ? ((const float4*)bias)[cg] : make_float4(0.f,0.f,0.f,0.f);
    #pragma unroll
    for (int r=0;r<8;r++){
        size_t row = row0 + (kg<<3) + r;
        float c0,c1,c2,c3;
        upk(acc[r][0],c0,c1); upk(acc[r][1],c2,c3);
        float4 o = make_float4(c0+bv.x, c1+bv.y, c2+bv.z, c3+bv.w);
        if (flags&1){ o.x=fmaxf(o.x,0.f); o.y=fmaxf(o.y,0.f); o.z=fmaxf(o.z,0.f); o.w=fmaxf(o.w,0.f); }
        if (flags&4){
            float4 ad = ((const float4*)addsrc)[row*32 + cg];
            o.x+=ad.x; o.y+=ad.y; o.z+=ad.z; o.w+=ad.w;
        }
        ((float4*)C)[row*32 + cg] = o;
    }
}

// ---------------- maxpool over K with BN+relu ----------------
__global__ void k_maxpool(const float* __restrict__ bg, const float* __restrict__ bb){
    int bs = blockIdx.x, t = threadIdx.x;
    float m = g_m1[t], rv = rsqrtf(g_v1[t]+EPSV), ga=bg[t], be=bb[t];
    float best = -1e30f;
    #pragma unroll
    for (int k=0;k<KNN;k++){
        float v = g_h1[((size_t)bs*KNN+k)*FD + t];
        v = fmaxf((v-m)*rv*ga + be, 0.f);
        best = fmaxf(best, v);
    }
    g_newfeat[(size_t)bs*FD+t] = best;
}

// ---------------- bias fold: bqc = b_kern @ w_q ----------------
__global__ void k_foldb(const float* __restrict__ bk, const float* __restrict__ wq){
    int t = threadIdx.x;
    float s = 0.f;
    for (int i=0;i<FD;i++) s += bk[i]*wq[i*FD+t];
    g_bqc[t] = s;
}

// ---------------- fused posenc + att1 + att2 + softmax + weighted sum ----------------
// smem: Wpe(16384) W1(16384) W2(16384) bufA(4096) peS(4096) = 229376 B
__global__ __launch_bounds__(128) void k_attfused(
        const float* __restrict__ xyzp,
        const float* __restrict__ pe_w1, const float* __restrict__ pe_b1,
        const float* __restrict__ pe_b2,
        const float* __restrict__ at_b1, const float* __restrict__ at_b2,
        const float* __restrict__ pe_w2, const float* __restrict__ at_w1,
        const float* __restrict__ at_w2){
    extern __shared__ float sm[];
    float* Wpe  = sm;
    float* W1   = sm + 16384;
    float* W2   = sm + 32768;
    float* bufA = sm + 49152;        // [32][128]
    float* peS  = sm + 49152 + 4096; // [32][128]
    __shared__ int   idxs[32];
    __shared__ float pd[32][4];

    int t = threadIdx.x, kg = t>>5, cg = t&31;
    for (int i=t;i<4096;i+=128){
        ((float4*)Wpe)[i]=((const float4*)pe_w2)[i];
        ((float4*)W1 )[i]=((const float4*)at_w1)[i];
        ((float4*)W2 )[i]=((const float4*)at_w2)[i];
    }
    float w0=pe_w1[t], w1=pe_w1[FD+t], w2=pe_w1[2*FD+t], w3=pe_w1[3*FD+t];
    float b1=pe_b1[t];
    float4 pb2=((const float4*)pe_b2)[cg];
    float4 ab1=((const float4*)at_b1)[cg];
    float4 ab2=((const float4*)at_b2)[cg];
    const float inv = 0.08838834764831845f; // 1/sqrt(128)

    for (int tp=blockIdx.x; tp<BQ*NP/2; tp+=gridDim.x){
        int bn0 = tp*2, b = bn0>>13;
        __syncthreads();  // prev iter's softmax done before idx/pd/bufA rewrites
        if (t<32){
            int k=t, bn=bn0+(k>>4);
            int id = g_idx_up[(size_t)bn*KNN + (k&15)];
            idxs[k]=id;
            float4 qp=((const float4*)xyzp)[bn];
            float4 np=((const float4*)g_new_xyzp)[b*SP+id];
            pd[k][0]=qp.x-np.x; pd[k][1]=qp.y-np.y; pd[k][2]=qp.z-np.z; pd[k][3]=qp.w-np.w;
        }
        float q0=g_q[(size_t)bn0*FD+t], q1=g_q[((size_t)bn0+1)*FD+t];
        __syncthreads();
        // build0: relu(pdiff @ pe_w1 + pe_b1)
        #pragma unroll
        for (int k=0;k<32;k++){
            float v = b1 + pd[k][0]*w0 + pd[k][1]*w1 + pd[k][2]*w2 + pd[k][3]*w3;
            bufA[k*FD+t] = fmaxf(v, 0.f);
        }
        __syncthreads();
        u64 acc[8][2];
        gemm32_core(Wpe, bufA, kg, cg, acc);
        __syncthreads();
        #pragma unroll
        for (int r=0;r<8;r++){
            float c0,c1,c2,c3; upk(acc[r][0],c0,c1); upk(acc[r][1],c2,c3);
            float4 o = make_float4(c0+pb2.x, c1+pb2.y, c2+pb2.z, c3+pb2.w);
            ((float4*)(peS + ((kg<<3)+r)*FD))[cg] = o;
        }
        __syncthreads();
        // build1: q - k + pe
        #pragma unroll
        for (int k=0;k<32;k++){
            int id = idxs[k];
            float kv = g_ktab[((size_t)(b*SP+id))*FD + t];
            float qv = (k<16) ? q0 : q1;
            bufA[k*FD+t] = qv - kv + peS[k*FD+t];
        }
        __syncthreads();
        gemm32_core(W1, bufA, kg, cg, acc);
        __syncthreads();
        #pragma unroll
        for (int r=0;r<8;r++){
            float c0,c1,c2,c3; upk(acc[r][0],c0,c1); upk(acc[r][1],c2,c3);
            float4 o = make_float4(fmaxf(c0+ab1.x,0.f), fmaxf(c1+ab1.y,0.f),
                                   fmaxf(c2+ab1.z,0.f), fmaxf(c3+ab1.w,0.f));
            ((float4*)(bufA + ((kg<<3)+r)*FD))[cg] = o;
        }
        __syncthreads();
        gemm32_core(W2, bufA, kg, cg, acc);
        __syncthreads();
        #pragma unroll
        for (int r=0;r<8;r++){
            float c0,c1,c2,c3; upk(acc[r][0],c0,c1); upk(acc[r][1],c2,c3);
            float4 o = make_float4(c0+ab2.x, c1+ab2.y, c2+ab2.z, c3+ab2.w);
            ((float4*)(bufA + ((kg<<3)+r)*FD))[cg] = o;
        }
        __syncthreads();
        // softmax over K per point per channel + weighted sum of (v + pe)
        #pragma unroll
        for (int p=0;p<2;p++){
            float s[16], mx=-1e30f;
            #pragma unroll
            for (int k=0;k<16;k++){ s[k]=bufA[(p*16+k)*FD+t]*inv; mx=fmaxf(mx,s[k]); }
            float den=0.f;
            #pragma unroll
            for (int k=0;k<16;k++){ s[k]=expf(s[k]-mx); den+=s[k]; }
            float rden=1.f/den, r=0.f;
            #pragma unroll
            for (int k=0;k<16;k++){
                int id = idxs[p*16+k];
                float v = g_vtab[((size_t)(b*SP+id))*FD + t] + peS[(p*16+k)*FD+t];
                r += (s[k]*rden) * v;
            }
            g_res[((size_t)bn0+p)*FD + t] = r;
        }
    }
}

extern "C" void kernel_launch(void* const* d_in, const int* in_sizes, int n_in,
                              void* d_out, int out_size){
    const float* xyzp     = (const float*)d_in[0];
    const float* features = (const float*)d_in[1];
    const float* ln_g     = (const float*)d_in[2];
    const float* ln_b     = (const float*)d_in[3];
    const float* td_w0    = (const float*)d_in[4];
    const float* td_b0    = (const float*)d_in[5];
    const float* td_bn0_g = (const float*)d_in[6];
    const float* td_bn0_b = (const float*)d_in[7];
    const float* td_w1    = (const float*)d_in[8];
    const float* td_b1    = (const float*)d_in[9];
    const float* td_bn1_g = (const float*)d_in[10];
    const float* td_bn1_b = (const float*)d_in[11];
    const float* w_kern   = (const float*)d_in[12];
    const float* b_kern   = (const float*)d_in[13];
    const float* w_gkern  = (const float*)d_in[14];
    const float* b_gkern  = (const float*)d_in[15];
    const float* w_agg    = (const float*)d_in[16];
    const float* b_agg    = (const float*)d_in[17];
    const float* w_q      = (const float*)d_in[18];
    const float* w_k      = (const float*)d_in[19];
    const float* w_v      = (const float*)d_in[20];
    const float* pe_w1    = (const float*)d_in[21];
    const float* pe_b1    = (const float*)d_in[22];
    const float* pe_w2    = (const float*)d_in[23];
    const float* pe_b2    = (const float*)d_in[24];
    const float* at_w1    = (const float*)d_in[25];
    const float* at_b1    = (const float*)d_in[26];
    const float* at_w2    = (const float*)d_in[27];
    const float* at_b2    = (const float*)d_in[28];
    float* out = (float*)d_out;

    float *p_feats,*p_q,*p_h0,*p_h1,*p_part,*p_m0,*p_v0,*p_m1,*p_v1;
    float *p_newfeat,*p_newx,*p_ktab,*p_vtab,*p_res,*p_wqc,*p_bqc;
    cudaGetSymbolAddress((void**)&p_feats,   g_feats);
    cudaGetSymbolAddress((void**)&p_q,       g_q);
    cudaGetSymbolAddress((void**)&p_h0,      g_h0);
    cudaGetSymbolAddress((void**)&p_h1,      g_h1);
    cudaGetSymbolAddress((void**)&p_part,    g_part);
    cudaGetSymbolAddress((void**)&p_m0,      g_m0);
    cudaGetSymbolAddress((void**)&p_v0,      g_v0);
    cudaGetSymbolAddress((void**)&p_m1,      g_m1);
    cudaGetSymbolAddress((void**)&p_v1,      g_v1);
    cudaGetSymbolAddress((void**)&p_newfeat, g_newfeat);
    cudaGetSymbolAddress((void**)&p_newx,    g_newx);
    cudaGetSymbolAddress((void**)&p_ktab,    g_ktab);
    cudaGetSymbolAddress((void**)&p_vtab,    g_vtab);
    cudaGetSymbolAddress((void**)&p_res,     g_res);
    cudaGetSymbolAddress((void**)&p_wqc,     g_wqc);
    cudaGetSymbolAddress((void**)&p_bqc,     g_bqc);

    const int SM_PTS   = 3*NP*4;                 // 98304
    const int SM_H0    = (131*128 + 131*16)*4;   // 75456
    const int SM_GEMM  = (16384 + 4096)*4;       // 81920
    const int SM_FUSE  = (3*16384 + 2*4096)*4;   // 229376
    cudaFuncSetAttribute(k_fps,     cudaFuncAttributeMaxDynamicSharedMemorySize, SM_PTS);
    cudaFuncSetAttribute(k_knn_dn,  cudaFuncAttributeMaxDynamicSharedMemorySize, SM_PTS);
    cudaFuncSetAttribute(k_h0,      cudaFuncAttributeMaxDynamicSharedMemorySize, SM_H0);
    cudaFuncSetAttribute(k_gemm128, cudaFuncAttributeMaxDynamicSharedMemorySize, SM_GEMM);
    cudaFuncSetAttribute(k_attfused,cudaFuncAttributeMaxDynamicSharedMemorySize, SM_FUSE);

    k_layernorm<<<BQ*NP, 128>>>(features, ln_g, ln_b, p_feats);
    k_fps<<<BQ, 1024, SM_PTS>>>(xyzp);
    k_knn_dn<<<BQ*16, 256, SM_PTS>>>(xyzp);
    k_knn_up<<<BQ*1024, 256>>>(xyzp);
    k_h0<<<BQ*SP, 128, SM_H0>>>(xyzp, td_w0, td_b0);
    k_stats_part<<<64, 128>>>(p_h0, BQ*SP*KNN, p_part);
    k_stats_final<<<1, 128>>>(p_part, BQ*SP*KNN, p_m0, p_v0);
    k_gemm128<<<BQ*SP*KNN/32, 128, SM_GEMM>>>(p_h0, td_w1, td_b1, p_h1, 2,
                                              p_m0, p_v0, td_bn0_g, td_bn0_b, 0);
    k_stats_part<<<64, 128>>>(p_h1, BQ*SP*KNN, p_part);
    k_stats_final<<<1, 128>>>(p_part, BQ*SP*KNN, p_m1, p_v1);
    k_maxpool<<<BQ*SP, 128>>>(td_bn1_g, td_bn1_b);
    // fold: Wqc = w_kern @ w_q ; bqc = b_kern @ w_q ; q = feats @ Wqc + bqc
    k_gemm128<<<FD/32, 128, SM_GEMM>>>(w_kern, w_q, 0, p_wqc, 0, 0,0,0,0, 0);
    k_foldb<<<1, 128>>>(b_kern, w_q);
    k_gemm128<<<BQ*NP/32, 128, SM_GEMM>>>(p_feats, p_wqc, p_bqc, p_q, 0, 0,0,0,0, 0);
    k_gemm128<<<BQ*SP/32, 128, SM_GEMM>>>(p_newfeat, w_gkern, b_gkern, p_newx, 0, 0,0,0,0, 0);
    k_gemm128<<<BQ*SP/32, 128, SM_GEMM>>>(p_newx, w_k, 0, p_ktab, 0, 0,0,0,0, 0);
    k_gemm128<<<BQ*SP/32, 128, SM_GEMM>>>(p_newx, w_v, 0, p_vtab, 0, 0,0,0,0, 0);
    k_attfused<<<592, 128, SM_FUSE>>>(xyzp, pe_w1, pe_b1, pe_b2, at_b1, at_b2,
                                      pe_w2, at_w1, at_w2);
    k_gemm128<<<BQ*NP/32, 128, SM_GEMM>>>(p_res, w_agg, b_agg, out, 4, 0,0,0,0, p_feats);
}

// round 5
// speedup vs baseline: 1.4356x; 1.2771x over previous
#include <cuda_runtime.h>
#include <math.h>

#define BQ 4
#define NP 8192
#define SP 512
#define KNN 16
#define FD 128
#define EPSV 1e-5f
#define AST 66
typedef unsigned long long u64;

__device__ float g_feats[BQ*NP*FD];
__device__ float g_q[BQ*NP*FD];
__device__ int   g_fps[BQ*SP];
__device__ int   g_idx_dn[BQ*SP*KNN];
__device__ float g_new_xyz[BQ*SP*3];
__device__ float g_new_xyzp[BQ*SP*4];
__device__ float g_h0[BQ*SP*KNN*FD];
__device__ float g_h1[BQ*SP*KNN*FD];
__device__ float g_part[64*2*FD];
__device__ float g_m0[FD]; __device__ float g_v0[FD];
__device__ float g_m1[FD]; __device__ float g_v1[FD];
__device__ float g_newfeat[BQ*SP*FD];
__device__ float g_newx[BQ*SP*FD];
__device__ float g_ktab[BQ*SP*FD];
__device__ float g_vtab[BQ*SP*FD];
__device__ int   g_idx_up[BQ*NP*KNN];
__device__ float g_pe[67108864];
__device__ float g_res[BQ*NP*FD];
__device__ float g_wqc[FD*FD];
__device__ float g_bqc[FD];

// ---------- f32x2 packed helpers ----------
__device__ __forceinline__ u64 pk2(float a){
    u64 r; asm("mov.b64 %0,{%1,%1};" : "=l"(r) : "f"(a)); return r;
}
__device__ __forceinline__ void fma2(u64& d, u64 a, u64 b){
    asm("fma.rn.f32x2 %0,%1,%2,%0;" : "+l"(d) : "l"(a), "l"(b));
}
__device__ __forceinline__ void upk(u64 v, float& lo, float& hi){
    asm("mov.b64 {%0,%1},%2;" : "=f"(lo), "=f"(hi) : "l"(v));
}

// ---- 32-row core (128 threads) : Ash [32][128] row-major, W [128][128] ----
__device__ __forceinline__ void gemm32_core(const float* __restrict__ Wsh,
                                            const float* __restrict__ Ash,
                                            int kg, int cg, u64 acc[8][2]){
    #pragma unroll
    for (int r=0;r<8;r++){ acc[r][0]=0ull; acc[r][1]=0ull; }
    const float* arow = Ash + (kg<<3)*FD;
    #pragma unroll 4
    for (int i=0;i<FD;i++){
        ulonglong2 w = *(const ulonglong2*)(Wsh + i*FD + (cg<<2));
        #pragma unroll
        for (int r=0;r<8;r++){
            u64 a2 = pk2(arow[r*FD + i]);
            fma2(acc[r][0], a2, w.x);
            fma2(acc[r][1], a2, w.y);
        }
    }
}

// ---- 64-row core (256 threads, 8 warps). Ash TRANSPOSED [128 chan][64 row] stride AST.
// warp w -> rows 8w..8w+7 (4 row-pairs), cg -> cols 4cg..4cg+3.
__device__ __forceinline__ void gemm64_core(const float* __restrict__ Wsh,
                                            const float* __restrict__ Ash,
                                            int w, int cg, u64 acc[4][4]){
    #pragma unroll
    for (int rp=0;rp<4;rp++){
        #pragma unroll
        for (int c=0;c<4;c++) acc[rp][c]=0ull;
    }
    #pragma unroll 4
    for (int i=0;i<FD;i++){
        float4 wv = *(const float4*)(Wsh + i*FD + (cg<<2));
        u64 w0=pk2(wv.x), w1=pk2(wv.y), w2=pk2(wv.z), w3=pk2(wv.w);
        const float* ab = Ash + i*AST + (w<<3);
        u64 a0=*(const u64*)(ab+0);
        u64 a1=*(const u64*)(ab+2);
        u64 a2=*(const u64*)(ab+4);
        u64 a3=*(const u64*)(ab+6);
        fma2(acc[0][0],a0,w0); fma2(acc[0][1],a0,w1); fma2(acc[0][2],a0,w2); fma2(acc[0][3],a0,w3);
        fma2(acc[1][0],a1,w0); fma2(acc[1][1],a1,w1); fma2(acc[1][2],a1,w2); fma2(acc[1][3],a1,w3);
        fma2(acc[2][0],a2,w0); fma2(acc[2][1],a2,w1); fma2(acc[2][2],a2,w2); fma2(acc[2][3],a2,w3);
        fma2(acc[3][0],a3,w0); fma2(acc[3][1],a3,w1); fma2(acc[3][2],a3,w2); fma2(acc[3][3],a3,w3);
    }
}

// ---------------- layernorm ----------------
__global__ void k_layernorm(const float* __restrict__ x, const float* __restrict__ g,
                            const float* __restrict__ b, float* __restrict__ out){
    int row = blockIdx.x, t = threadIdx.x;
    __shared__ float sh[8];
    float v = x[(size_t)row*FD + t];
    float s = v;
    #pragma unroll
    for (int o=16;o;o>>=1) s += __shfl_xor_sync(0xffffffffu, s, o);
    if ((t&31)==0) sh[t>>5]=s;
    __syncthreads();
    float mean = (sh[0]+sh[1]+sh[2]+sh[3]) * (1.0f/FD);
    float d = v - mean;
    float s2 = d*d;
    #pragma unroll
    for (int o=16;o;o>>=1) s2 += __shfl_xor_sync(0xffffffffu, s2, o);
    if ((t&31)==0) sh[4+(t>>5)]=s2;
    __syncthreads();
    float var = (sh[4]+sh[5]+sh[6]+sh[7]) * (1.0f/FD);
    out[(size_t)row*FD+t] = d * rsqrtf(var + EPSV) * g[t] + b[t];
}

// ---------------- FPS ----------------
__global__ void k_fps(const float* __restrict__ xyzp){
    extern __shared__ float sm[];
    float* xs = sm; float* ys = sm + NP; float* zs = sm + 2*NP;
    int b = blockIdx.x, t = threadIdx.x;
    float px[8], py[8], pz[8], md[8];
    #pragma unroll
    for (int j=0;j<8;j++){
        int i = t + j*1024;
        float4 p = ((const float4*)xyzp)[(size_t)b*NP + i];
        px[j]=p.x; py[j]=p.y; pz[j]=p.z; md[j]=1e10f;
        xs[i]=p.x; ys[i]=p.y; zs[i]=p.z;
    }
    __shared__ u64 warpbest[32];
    __shared__ int s_last;
    if (t==0){ g_fps[b*SP]=0; s_last=0; }
    __syncthreads();
    int last = 0;
    for (int s=1;s<SP;s++){
        float lx=xs[last], ly=ys[last], lz=zs[last];
        u64 best=0;
        #pragma unroll
        for (int j=0;j<8;j++){
            float dx=px[j]-lx, dy=py[j]-ly, dz=pz[j]-lz;
            float d = dx*dx+dy*dy+dz*dz;
            md[j] = fminf(md[j], d);
            u64 key = ((u64)__float_as_uint(md[j])<<32) | (unsigned)(NP-1 - (t + j*1024));
            best = key > best ? key : best;
        }
        #pragma unroll
        for (int o=16;o;o>>=1){
            u64 oth = __shfl_xor_sync(0xffffffffu, best, o);
            best = oth > best ? oth : best;
        }
        if ((t&31)==0) warpbest[t>>5]=best;
        __syncthreads();
        if (t<32){
            u64 bb = warpbest[t];
            #pragma unroll
            for (int o=16;o;o>>=1){
                u64 oth = __shfl_xor_sync(0xffffffffu, bb, o);
                bb = oth > bb ? oth : bb;
            }
            if (t==0){ s_last = NP-1 - (int)(bb & 0xffffffffu); g_fps[b*SP+s]=s_last; }
        }
        __syncthreads();
        last = s_last;
    }
}

// ---------------- knn: 512 fps pts vs 8192 refs ----------------
__global__ void k_knn_dn(const float* __restrict__ xyzp){
    extern __shared__ float sm[];
    float* xs = sm; float* ys = sm+NP; float* zs = sm+2*NP;
    int b = blockIdx.x >> 4, blk = blockIdx.x & 15;
    int t = threadIdx.x, w = t>>5, lane = t&31;
    for (int i=t;i<NP;i+=256){
        float4 p = ((const float4*)xyzp)[(size_t)b*NP + i];
        xs[i]=p.x; ys[i]=p.y; zs[i]=p.z;
    }
    __syncthreads();
    for (int qi=0; qi<4; qi++){
        int s = blk*32 + w*4 + qi;
        int qidx = g_fps[b*SP+s];
        float qx=xs[qidx], qy=ys[qidx], qz=zs[qidx];
        if (lane==0){
            g_new_xyz[(b*SP+s)*3+0]=qx; g_new_xyz[(b*SP+s)*3+1]=qy; g_new_xyz[(b*SP+s)*3+2]=qz;
        }
        u64 kk[16];
        #pragma unroll
        for (int j=0;j<16;j++) kk[j]=~0ull;
        for (int r=lane; r<NP; r+=32){
            float dx=xs[r]-qx, dy=ys[r]-qy, dz=zs[r]-qz;
            float d = dx*dx+dy*dy+dz*dz;
            u64 key = ((u64)__float_as_uint(d)<<32) | (unsigned)r;
            if (key < kk[15]){
                #pragma unroll
                for (int j=0;j<16;j++){
                    u64 lo = kk[j] < key ? kk[j] : key;
                    u64 hi = kk[j] < key ? key : kk[j];
                    kk[j]=lo; key=hi;
                }
            }
        }
        u64 prev = 0;
        for (int r=0;r<16;r++){
            u64 thr = (r==0) ? 0ull : prev + 1ull;
            u64 loc = ~0ull;
            #pragma unroll
            for (int j=0;j<16;j++){
                u64 v = kk[j];
                if (v >= thr && v < loc) loc = v;
            }
            #pragma unroll
            for (int o=16;o;o>>=1){
                u64 oth = __shfl_xor_sync(0xffffffffu, loc, o);
                loc = oth < loc ? oth : loc;
            }
            prev = loc;
            if (lane==0){
                int id = (int)(loc & 0xffffffffu);
                g_idx_dn[(b*SP+s)*KNN + r] = id;
                if (r==0) ((float4*)g_new_xyzp)[b*SP+s] = ((const float4*)xyzp)[(size_t)b*NP + id];
            }
        }
    }
}

// ---------------- knn: 8192 pts vs 512 fps pts ----------------
__global__ void k_knn_up(const float* __restrict__ xyzp){
    __shared__ float rx[SP], ry[SP], rz[SP];
    int t=threadIdx.x, w=t>>5, lane=t&31;
    int b = blockIdx.x >> 10;
    int n = (blockIdx.x & 1023)*8 + w;
    for (int i=t;i<SP;i+=256){
        rx[i]=g_new_xyz[(i+b*SP)*3+0]; ry[i]=g_new_xyz[(i+b*SP)*3+1]; rz[i]=g_new_xyz[(i+b*SP)*3+2];
    }
    __syncthreads();
    float4 qp = ((const float4*)xyzp)[(size_t)b*NP + n];
    u64 kk[16];
    #pragma unroll
    for (int j=0;j<16;j++) kk[j]=~0ull;
    for (int r=lane; r<SP; r+=32){
        float dx=rx[r]-qp.x, dy=ry[r]-qp.y, dz=rz[r]-qp.z;
        float d = dx*dx+dy*dy+dz*dz;
        u64 key = ((u64)__float_as_uint(d)<<32) | (unsigned)r;
        if (key < kk[15]){
            #pragma unroll
            for (int j=0;j<16;j++){
                u64 lo = kk[j] < key ? kk[j] : key;
                u64 hi = kk[j] < key ? key : kk[j];
                kk[j]=lo; key=hi;
            }
        }
    }
    u64 prev = 0;
    for (int r=0;r<16;r++){
        u64 thr = (r==0) ? 0ull : prev + 1ull;
        u64 loc = ~0ull;
        #pragma unroll
        for (int j=0;j<16;j++){
            u64 v = kk[j];
            if (v >= thr && v < loc) loc = v;
        }
        #pragma unroll
        for (int o=16;o;o>>=1){
            u64 oth = __shfl_xor_sync(0xffffffffu, loc, o);
            loc = oth < loc ? oth : loc;
        }
        prev = loc;
        if (lane==0) g_idx_up[((size_t)b*NP+n)*KNN + r] = (int)(loc & 0xffffffffu);
    }
}

// ---------------- scalar tile core for 131-K h0 ----------------
__device__ __forceinline__ void mm_tile(const float* Wsh, const float* Ash,
                                        int kg, int cg, float acc[4][4], int kdim){
    #pragma unroll 4
    for (int i=0;i<kdim;i++){
        float4 wv = *(const float4*)(Wsh + i*128 + (cg<<2));
        float a0=Ash[i*16+(kg<<2)+0];
        float a1=Ash[i*16+(kg<<2)+1];
        float a2=Ash[i*16+(kg<<2)+2];
        float a3=Ash[i*16+(kg<<2)+3];
        acc[0][0]+=a0*wv.x; acc[0][1]+=a0*wv.y; acc[0][2]+=a0*wv.z; acc[0][3]+=a0*wv.w;
        acc[1][0]+=a1*wv.x; acc[1][1]+=a1*wv.y; acc[1][2]+=a1*wv.z; acc[1][3]+=a1*wv.w;
        acc[2][0]+=a2*wv.x; acc[2][1]+=a2*wv.y; acc[2][2]+=a2*wv.z; acc[2][3]+=a2*wv.w;
        acc[3][0]+=a3*wv.x; acc[3][1]+=a3*wv.y; acc[3][2]+=a3*wv.z; acc[3][3]+=a3*wv.w;
    }
}

__global__ void k_h0(const float* __restrict__ xyzp, const float* __restrict__ tw0,
                     const float* __restrict__ tb0){
    extern __shared__ float sm[];
    float* Wsh = sm;
    float* Ash = Wsh + 131*128;
    __shared__ int idxs[16];
    __shared__ float nxyz[3];
    int t = threadIdx.x, bs = blockIdx.x, b = bs >> 9;
    for (int i=t;i<131*128;i+=128) Wsh[i]=tw0[i];
    if (t<16) idxs[t] = g_idx_dn[bs*KNN+t];
    if (t<3)  nxyz[t] = g_new_xyz[bs*3+t];
    __syncthreads();
    #pragma unroll
    for (int k=0;k<KNN;k++){
        int id = idxs[k];
        float v;
        if (t<3) v = xyzp[((size_t)b*NP+id)*4 + t] - nxyz[t];
        else     v = g_feats[((size_t)b*NP+id)*FD + (t-3)];
        Ash[t*16+k]=v;
        if (t<3) Ash[(128+t)*16+k] = g_feats[((size_t)b*NP+id)*FD + (125+t)];
    }
    __syncthreads();
    int kg=t>>5, cg=t&31;
    float acc[4][4]={};
    mm_tile(Wsh, Ash, kg, cg, acc, 131);
    float4 bv = *(const float4*)(tb0 + (cg<<2));
    #pragma unroll
    for (int kk=0;kk<4;kk++){
        float4 o = make_float4(acc[kk][0]+bv.x, acc[kk][1]+bv.y, acc[kk][2]+bv.z, acc[kk][3]+bv.w);
        ((float4*)g_h0)[((size_t)bs*KNN + 4*kg+kk)*32 + cg] = o;
    }
}

// ---------------- batchnorm stats ----------------
__global__ void k_stats_part(const float* __restrict__ X, int nrows, float* __restrict__ part){
    int t=threadIdx.x, blk=blockIdx.x;
    int chunk = nrows/64;
    float s=0.f, s2=0.f;
    for (int r=0;r<chunk;r++){
        float v = X[((size_t)(blk*chunk+r))*FD + t];
        s += v; s2 += v*v;
    }
    part[blk*2*FD + t] = s;
    part[blk*2*FD + FD + t] = s2;
}
__global__ void k_stats_final(const float* __restrict__ part, int nrows,
                              float* __restrict__ mean, float* __restrict__ var){
    int t=threadIdx.x;
    float s=0.f, s2=0.f;
    for (int i=0;i<64;i++){ s += part[i*2*FD+t]; s2 += part[i*2*FD+FD+t]; }
    float m = s/(float)nrows;
    mean[t]=m;
    var[t]=s2/(float)nrows - m*m;
}

// ---------------- 32-row f32x2 GEMM (128->128) ----------------
__global__ __launch_bounds__(128) void k_gemm128(
        const float* __restrict__ A, const float* __restrict__ W,
        const float* __restrict__ bias, float* __restrict__ C, int flags,
        const float* __restrict__ bnm, const float* __restrict__ bnv,
        const float* __restrict__ bng, const float* __restrict__ bnb,
        const float* __restrict__ addsrc){
    extern __shared__ float sm[];
    float* Wsh = sm; float* Ash = sm + 16384;
    int t=threadIdx.x;
    size_t row0 = (size_t)blockIdx.x*32;
    for (int i=t;i<4096;i+=128) ((float4*)Wsh)[i]=((const float4*)W)[i];
    float bm=0.f, brv=1.f, bg=1.f, bb=0.f;
    if (flags&2){ bm=bnm[t]; brv=rsqrtf(bnv[t]+EPSV); bg=bng[t]; bb=bnb[t]; }
    #pragma unroll
    for (int k=0;k<32;k++){
        float v = A[(row0+k)*FD + t];
        if (flags&2) v = fmaxf((v-bm)*brv*bg + bb, 0.f);
        Ash[k*FD+t]=v;
    }
    __syncthreads();
    int kg=t>>5, cg=t&31;
    u64 acc[8][2];
    gemm32_core(Wsh, Ash, kg, cg, acc);
    float4 bv = bias ? ((const float4*)bias)[cg] : make_float4(0.f,0.f,0.f,0.f);
    #pragma unroll
    for (int r=0;r<8;r++){
        size_t row = row0 + (kg<<3) + r;
        float c0,c1,c2,c3;
        upk(acc[r][0],c0,c1); upk(acc[r][1],c2,c3);
        float4 o = make_float4(c0+bv.x, c1+bv.y, c2+bv.z, c3+bv.w);
        if (flags&1){ o.x=fmaxf(o.x,0.f); o.y=fmaxf(o.y,0.f); o.z=fmaxf(o.z,0.f); o.w=fmaxf(o.w,0.f); }
        if (flags&4){
            float4 ad = ((const float4*)addsrc)[row*32 + cg];
            o.x+=ad.x; o.y+=ad.y; o.z+=ad.z; o.w+=ad.w;
        }
        ((float4*)C)[row*32 + cg] = o;
    }
}

// ---------------- maxpool over K with BN+relu ----------------
__global__ void k_maxpool(const float* __restrict__ bg, const float* __restrict__ bb){
    int bs = blockIdx.x, t = threadIdx.x;
    float m = g_m1[t], rv = rsqrtf(g_v1[t]+EPSV), ga=bg[t], be=bb[t];
    float best = -1e30f;
    #pragma unroll
    for (int k=0;k<KNN;k++){
        float v = g_h1[((size_t)bs*KNN+k)*FD + t];
        v = fmaxf((v-m)*rv*ga + be, 0.f);
        best = fmaxf(best, v);
    }
    g_newfeat[(size_t)bs*FD+t] = best;
}

// ---------------- bias fold: bqc = b_kern @ w_q ----------------
__global__ void k_foldb(const float* __restrict__ bk, const float* __restrict__ wq){
    int t = threadIdx.x;
    float s = 0.f;
    for (int i=0;i<FD;i++) s += bk[i]*wq[i*FD+t];
    g_bqc[t] = s;
}

// ---------------- posenc: 64-row tiles, 256 threads, persistent ----------------
__global__ __launch_bounds__(256,1) void k_posenc64(
        const float* __restrict__ xyzp,
        const float* __restrict__ pe_w1, const float* __restrict__ pe_b1,
        const float* __restrict__ pe_w2, const float* __restrict__ pe_b2){
    extern __shared__ float sm[];
    float* Wsh = sm;            // 16384
    float* Ash = sm + 16384;    // 128*AST
    __shared__ float pd[64][4];
    int t=threadIdx.x, w=t>>5, cg=t&31, c=t&127, half=t>>7;
    for (int i=t;i<4096;i+=256) ((float4*)Wsh)[i]=((const float4*)pe_w2)[i];
    float w0=pe_w1[c], w1=pe_w1[FD+c], w2=pe_w1[2*FD+c], w3=pe_w1[3*FD+c];
    float bb1=pe_b1[c];
    float4 pb2=((const float4*)pe_b2)[cg];
    for (int tp=blockIdx.x; tp<BQ*NP/4; tp+=gridDim.x){
        int bn0=tp*4, b=bn0>>13;
        __syncthreads();
        if (t<64){
            int k=t, bn=bn0+(k>>4);
            int id=g_idx_up[(size_t)bn*KNN+(k&15)];
            float4 qp=((const float4*)xyzp)[bn];
            float4 np=((const float4*)g_new_xyzp)[b*SP+id];
            pd[k][0]=qp.x-np.x; pd[k][1]=qp.y-np.y; pd[k][2]=qp.z-np.z; pd[k][3]=qp.w-np.w;
        }
        __syncthreads();
        #pragma unroll 8
        for (int kk=0;kk<32;kk++){
            int k=half*32+kk;
            float v = bb1 + pd[k][0]*w0 + pd[k][1]*w1 + pd[k][2]*w2 + pd[k][3]*w3;
            Ash[c*AST+k]=fmaxf(v,0.f);
        }
        __syncthreads();
        u64 acc[4][4];
        gemm64_core(Wsh, Ash, w, cg, acc);
        size_t base = (size_t)bn0*16;
        #pragma unroll
        for (int rp=0;rp<4;rp++){
            int r0=(w<<3)+(rp<<1);
            float l0,h0,l1,h1,l2,h2,l3,h3;
            upk(acc[rp][0],l0,h0); upk(acc[rp][1],l1,h1);
            upk(acc[rp][2],l2,h2); upk(acc[rp][3],l3,h3);
            ((float4*)g_pe)[(base+r0)*32 + cg]   = make_float4(l0+pb2.x,l1+pb2.y,l2+pb2.z,l3+pb2.w);
            ((float4*)g_pe)[(base+r0+1)*32 + cg] = make_float4(h0+pb2.x,h1+pb2.y,h2+pb2.z,h3+pb2.w);
        }
    }
}

// ---------------- fused att1+att2+softmax+sum: 64-row tiles, 256 thr, persistent ----------------
__global__ __launch_bounds__(256,1) void k_att12(
        const float* __restrict__ at_b1, const float* __restrict__ at_b2,
        const float* __restrict__ at_w1, const float* __restrict__ at_w2){
    extern __shared__ float sm[];
    float* W1   = sm;                 // 16384
    float* W2   = sm + 16384;         // 16384
    float* bufA = sm + 32768;         // 128*AST
    float* bufB = sm + 32768 + 128*AST;
    __shared__ int sidx[64];
    int t=threadIdx.x, w=t>>5, cg=t&31, c=t&127, half=t>>7;
    for (int i=t;i<4096;i+=256){
        ((float4*)W1)[i]=((const float4*)at_w1)[i];
        ((float4*)W2)[i]=((const float4*)at_w2)[i];
    }
    float4 ab1=((const float4*)at_b1)[cg];
    float4 ab2=((const float4*)at_b2)[cg];
    const float inv = 0.08838834764831845f;
    for (int tp=blockIdx.x; tp<BQ*NP/4; tp+=gridDim.x){
        int bn0=tp*4, b=bn0>>13;
        __syncthreads();
        if (t<64) sidx[t]=g_idx_up[(size_t)(bn0+(t>>4))*KNN + (t&15)];
        __syncthreads();
        float q0=g_q[(size_t)(bn0+0)*FD+c];
        float q1=g_q[(size_t)(bn0+1)*FD+c];
        float q2=g_q[(size_t)(bn0+2)*FD+c];
        float q3=g_q[(size_t)(bn0+3)*FD+c];
        #pragma unroll 4
        for (int kk=0;kk<32;kk++){
            int k=half*32+kk;
            int id=sidx[k];
            float kv=g_ktab[(size_t)(b*SP+id)*FD+c];
            float pe=g_pe[((size_t)bn0*16+k)*FD+c];
            float qv = (k<16)?q0 : (k<32)?q1 : (k<48)?q2 : q3;
            bufA[c*AST+k]=qv-kv+pe;
        }
        __syncthreads();
        u64 acc[4][4];
        gemm64_core(W1, bufA, w, cg, acc);
        #pragma unroll
        for (int rp=0;rp<4;rp++){
            int r0=(w<<3)+(rp<<1);
            #pragma unroll
            for (int cc=0;cc<4;cc++){
                float lo,hi; upk(acc[rp][cc],lo,hi);
                float bv = (cc==0)?ab1.x:(cc==1)?ab1.y:(cc==2)?ab1.z:ab1.w;
                bufB[((cg<<2)+cc)*AST + r0  ]=fmaxf(lo+bv,0.f);
                bufB[((cg<<2)+cc)*AST + r0+1]=fmaxf(hi+bv,0.f);
            }
        }
        __syncthreads();
        gemm64_core(W2, bufB, w, cg, acc);
        #pragma unroll
        for (int rp=0;rp<4;rp++){
            int r0=(w<<3)+(rp<<1);
            #pragma unroll
            for (int cc=0;cc<4;cc++){
                float lo,hi; upk(acc[rp][cc],lo,hi);
                float bv = (cc==0)?ab2.x:(cc==1)?ab2.y:(cc==2)?ab2.z:ab2.w;
                bufA[((cg<<2)+cc)*AST + r0  ]=lo+bv;
                bufA[((cg<<2)+cc)*AST + r0+1]=hi+bv;
            }
        }
        __syncthreads();
        #pragma unroll
        for (int j=0;j<2;j++){
            int item = t + 256*j;
            int p = item>>7, ch = item&127;
            float s[16], mx=-1e30f;
            #pragma unroll
            for (int k=0;k<16;k++){ s[k]=bufA[ch*AST + p*16 + k]*inv; mx=fmaxf(mx,s[k]); }
            float den=0.f;
            #pragma unroll
            for (int k=0;k<16;k++){ s[k]=expf(s[k]-mx); den+=s[k]; }
            float rden=1.f/den, r=0.f;
            #pragma unroll
            for (int k=0;k<16;k++){
                int id=sidx[p*16+k];
                float v=g_vtab[(size_t)(b*SP+id)*FD+ch] + g_pe[((size_t)bn0*16+p*16+k)*FD+ch];
                r += s[k]*rden*v;
            }
            g_res[(size_t)(bn0+p)*FD+ch]=r;
        }
    }
}

extern "C" void kernel_launch(void* const* d_in, const int* in_sizes, int n_in,
                              void* d_out, int out_size){
    const float* xyzp     = (const float*)d_in[0];
    const float* features = (const float*)d_in[1];
    const float* ln_g     = (const float*)d_in[2];
    const float* ln_b     = (const float*)d_in[3];
    const float* td_w0    = (const float*)d_in[4];
    const float* td_b0    = (const float*)d_in[5];
    const float* td_bn0_g = (const float*)d_in[6];
    const float* td_bn0_b = (const float*)d_in[7];
    const float* td_w1    = (const float*)d_in[8];
    const float* td_b1    = (const float*)d_in[9];
    const float* td_bn1_g = (const float*)d_in[10];
    const float* td_bn1_b = (const float*)d_in[11];
    const float* w_kern   = (const float*)d_in[12];
    const float* b_kern   = (const float*)d_in[13];
    const float* w_gkern  = (const float*)d_in[14];
    const float* b_gkern  = (const float*)d_in[15];
    const float* w_agg    = (const float*)d_in[16];
    const float* b_agg    = (const float*)d_in[17];
    const float* w_q      = (const float*)d_in[18];
    const float* w_k      = (const float*)d_in[19];
    const float* w_v      = (const float*)d_in[20];
    const float* pe_w1    = (const float*)d_in[21];
    const float* pe_b1    = (const float*)d_in[22];
    const float* pe_w2    = (const float*)d_in[23];
    const float* pe_b2    = (const float*)d_in[24];
    const float* at_w1    = (const float*)d_in[25];
    const float* at_b1    = (const float*)d_in[26];
    const float* at_w2    = (const float*)d_in[27];
    const float* at_b2    = (const float*)d_in[28];
    float* out = (float*)d_out;

    float *p_feats,*p_q,*p_h0,*p_h1,*p_part,*p_m0,*p_v0,*p_m1,*p_v1;
    float *p_newfeat,*p_newx,*p_ktab,*p_vtab,*p_res,*p_wqc,*p_bqc;
    cudaGetSymbolAddress((void**)&p_feats,   g_feats);
    cudaGetSymbolAddress((void**)&p_q,       g_q);
    cudaGetSymbolAddress((void**)&p_h0,      g_h0);
    cudaGetSymbolAddress((void**)&p_h1,      g_h1);
    cudaGetSymbolAddress((void**)&p_part,    g_part);
    cudaGetSymbolAddress((void**)&p_m0,      g_m0);
    cudaGetSymbolAddress((void**)&p_v0,      g_v0);
    cudaGetSymbolAddress((void**)&p_m1,      g_m1);
    cudaGetSymbolAddress((void**)&p_v1,      g_v1);
    cudaGetSymbolAddress((void**)&p_newfeat, g_newfeat);
    cudaGetSymbolAddress((void**)&p_newx,    g_newx);
    cudaGetSymbolAddress((void**)&p_ktab,    g_ktab);
    cudaGetSymbolAddress((void**)&p_vtab,    g_vtab);
    cudaGetSymbolAddress((void**)&p_res,     g_res);
    cudaGetSymbolAddress((void**)&p_wqc,     g_wqc);
    cudaGetSymbolAddress((void**)&p_bqc,     g_bqc);

    const int SM_PTS  = 3*NP*4;                   // 98304
    const int SM_H0   = (131*128 + 131*16)*4;     // 75456
    const int SM_GEMM = (16384 + 4096)*4;         // 81920
    const int SM_PE   = (16384 + 128*AST)*4;      // 99328
    const int SM_A12  = (32768 + 2*128*AST)*4;    // 198656
    cudaFuncSetAttribute(k_fps,      cudaFuncAttributeMaxDynamicSharedMemorySize, SM_PTS);
    cudaFuncSetAttribute(k_knn_dn,   cudaFuncAttributeMaxDynamicSharedMemorySize, SM_PTS);
    cudaFuncSetAttribute(k_h0,       cudaFuncAttributeMaxDynamicSharedMemorySize, SM_H0);
    cudaFuncSetAttribute(k_gemm128,  cudaFuncAttributeMaxDynamicSharedMemorySize, SM_GEMM);
    cudaFuncSetAttribute(k_posenc64, cudaFuncAttributeMaxDynamicSharedMemorySize, SM_PE);
    cudaFuncSetAttribute(k_att12,    cudaFuncAttributeMaxDynamicSharedMemorySize, SM_A12);

    k_layernorm<<<BQ*NP, 128>>>(features, ln_g, ln_b, p_feats);
    k_fps<<<BQ, 1024, SM_PTS>>>(xyzp);
    k_knn_dn<<<BQ*16, 256, SM_PTS>>>(xyzp);
    k_knn_up<<<BQ*1024, 256>>>(xyzp);
    k_h0<<<BQ*SP, 128, SM_H0>>>(xyzp, td_w0, td_b0);
    k_stats_part<<<64, 128>>>(p_h0, BQ*SP*KNN, p_part);
    k_stats_final<<<1, 128>>>(p_part, BQ*SP*KNN, p_m0, p_v0);
    k_gemm128<<<BQ*SP*KNN/32, 128, SM_GEMM>>>(p_h0, td_w1, td_b1, p_h1, 2,
                                              p_m0, p_v0, td_bn0_g, td_bn0_b, 0);
    k_stats_part<<<64, 128>>>(p_h1, BQ*SP*KNN, p_part);
    k_stats_final<<<1, 128>>>(p_part, BQ*SP*KNN, p_m1, p_v1);
    k_maxpool<<<BQ*SP, 128>>>(td_bn1_g, td_bn1_b);
    k_gemm128<<<FD/32, 128, SM_GEMM>>>(w_kern, w_q, 0, p_wqc, 0, 0,0,0,0, 0);
    k_foldb<<<1, 128>>>(b_kern, w_q);
    k_gemm128<<<BQ*NP/32, 128, SM_GEMM>>>(p_feats, p_wqc, p_bqc, p_q, 0, 0,0,0,0, 0);
    k_gemm128<<<BQ*SP/32, 128, SM_GEMM>>>(p_newfeat, w_gkern, b_gkern, p_newx, 0, 0,0,0,0, 0);
    k_gemm128<<<BQ*SP/32, 128, SM_GEMM>>>(p_newx, w_k, 0, p_ktab, 0, 0,0,0,0, 0);
    k_gemm128<<<BQ*SP/32, 128, SM_GEMM>>>(p_newx, w_v, 0, p_vtab, 0, 0,0,0,0, 0);
    k_posenc64<<<296, 256, SM_PE>>>(xyzp, pe_w1, pe_b1, pe_w2, pe_b2);
    k_att12<<<148, 256, SM_A12>>>(at_b1, at_b2, at_w1, at_w2);
    k_gemm128<<<BQ*NP/32, 128, SM_GEMM>>>(p_res, w_agg, b_agg, out, 4, 0,0,0,0, p_feats);
}